// round 2
// baseline (speedup 1.0000x reference)
#include <cuda_runtime.h>
#include <math.h>

#define LL 256
#define CC 128
#define HH 4
#define DD 32
#define NROW (LL*LL)          // 65536 rows of (s,l)

// ---------------- scratch (device globals; no allocation allowed) ----------
__device__ float g_x   [NROW*CC];   // layernormed pair act  [s*L+l][c]
__device__ float g_biasT[HH*LL*LL]; // bias transposed       [h][k][q]
__device__ float g_q   [NROW*CC];   // [ (s*H+h)*L + l ][d]
__device__ float g_k   [NROW*CC];
__device__ float g_v   [NROW*CC];
__device__ float g_gate[NROW*CC];   // sigmoid(x@wg+bg)      [s*L+l][c]
__device__ float g_wa  [NROW*CC];   // gated attention out   [s*L+l][c]

// ---------------- K1: LayerNorm + pair bias --------------------------------
__global__ void k_ln_bias(const float* __restrict__ pa,
                          const float* __restrict__ lng,
                          const float* __restrict__ lnb,
                          const float* __restrict__ wp) {
    int row  = blockIdx.x * 8 + threadIdx.y;    // 65536 rows, 8 per block
    int lane = threadIdx.x;                     // 32 lanes, float4 each
    const float4* src = (const float4*)(pa + (size_t)row * CC);
    float4 v = src[lane];

    float sum = v.x + v.y + v.z + v.w;
    #pragma unroll
    for (int o = 16; o; o >>= 1) sum += __shfl_xor_sync(0xffffffffu, sum, o);
    float mean = sum * (1.0f / CC);

    float d0 = v.x - mean, d1 = v.y - mean, d2 = v.z - mean, d3 = v.w - mean;
    float vs = d0*d0 + d1*d1 + d2*d2 + d3*d3;
    #pragma unroll
    for (int o = 16; o; o >>= 1) vs += __shfl_xor_sync(0xffffffffu, vs, o);
    float rstd = rsqrtf(vs * (1.0f / CC) + 1e-5f);

    int c = lane * 4;
    float4 gg = ((const float4*)lng)[lane];
    float4 bb = ((const float4*)lnb)[lane];
    float y0 = d0 * rstd * gg.x + bb.x;
    float y1 = d1 * rstd * gg.y + bb.y;
    float y2 = d2 * rstd * gg.z + bb.z;
    float y3 = d3 * rstd * gg.w + bb.w;
    float4 out = make_float4(y0, y1, y2, y3);
    ((float4*)(g_x + (size_t)row * CC))[lane] = out;

    // bias[h] = sum_c y_c * wp[c*4+h]  (wp is (C,H), H=4 -> one float4 per c)
    float4 w0 = ((const float4*)wp)[c + 0];
    float4 w1 = ((const float4*)wp)[c + 1];
    float4 w2 = ((const float4*)wp)[c + 2];
    float4 w3 = ((const float4*)wp)[c + 3];
    float a0 = y0*w0.x + y1*w1.x + y2*w2.x + y3*w3.x;
    float a1 = y0*w0.y + y1*w1.y + y2*w2.y + y3*w3.y;
    float a2 = y0*w0.z + y1*w1.z + y2*w2.z + y3*w3.z;
    float a3 = y0*w0.w + y1*w1.w + y2*w2.w + y3*w3.w;
    #pragma unroll
    for (int o = 16; o; o >>= 1) {
        a0 += __shfl_xor_sync(0xffffffffu, a0, o);
        a1 += __shfl_xor_sync(0xffffffffu, a1, o);
        a2 += __shfl_xor_sync(0xffffffffu, a2, o);
        a3 += __shfl_xor_sync(0xffffffffu, a3, o);
    }
    if (lane == 0) {
        int i = row >> 8;      // q index
        int j = row & 255;     // k index
        // store transposed: [h][k][q]
        g_biasT[0*NROW + j*LL + i] = a0;
        g_biasT[1*NROW + j*LL + i] = a1;
        g_biasT[2*NROW + j*LL + i] = a2;
        g_biasT[3*NROW + j*LL + i] = a3;
    }
}

// ---------------- K2: x @ {wq,wk,wv,wg}  -----------------------------------
// grid = (1024, 4); block = 256.  blockIdx.y selects the weight matrix.
__global__ void k_qkvg(const float* __restrict__ wq, const float* __restrict__ wk,
                       const float* __restrict__ wv, const float* __restrict__ wg,
                       const float* __restrict__ bg) {
    extern __shared__ float smem[];
    float* Ws = smem;            // 128*128
    float* As = smem + 128*128;  // 64*128

    int m = blockIdx.y;
    const float* W = (m == 0) ? wq : (m == 1) ? wk : (m == 2) ? wv : wg;
    int tid = threadIdx.x;

    for (int i = tid; i < 4096; i += 256)
        ((float4*)Ws)[i] = ((const float4*)W)[i];
    int row0 = blockIdx.x * 64;
    for (int i = tid; i < 2048; i += 256)
        ((float4*)As)[i] = ((const float4*)(g_x + (size_t)row0 * CC))[i];
    __syncthreads();

    int tcol = tid & 31, trow = tid >> 5;
    float acc[8][4];
    #pragma unroll
    for (int r = 0; r < 8; r++)
        acc[r][0] = acc[r][1] = acc[r][2] = acc[r][3] = 0.0f;

    #pragma unroll 4
    for (int k = 0; k < 128; k++) {
        float4 bf = ((float4*)(Ws + k * 128))[tcol];
        #pragma unroll
        for (int r = 0; r < 8; r++) {
            float a = As[(trow + r * 8) * 128 + k];
            acc[r][0] += a * bf.x;
            acc[r][1] += a * bf.y;
            acc[r][2] += a * bf.z;
            acc[r][3] += a * bf.w;
        }
    }

    int e0 = tcol * 4;
    if (m < 3) {
        float* dst = (m == 0) ? g_q : (m == 1) ? g_k : g_v;
        int h = e0 >> 5, d = e0 & 31;
        #pragma unroll
        for (int r = 0; r < 8; r++) {
            int grow = row0 + trow + r * 8;
            int s = grow >> 8, l = grow & 255;
            float4 o = make_float4(acc[r][0], acc[r][1], acc[r][2], acc[r][3]);
            *((float4*)(dst + ((size_t)((s * 4 + h) * 256 + l)) * 32 + d)) = o;
        }
    } else {
        float4 bgv = ((const float4*)bg)[tcol];
        #pragma unroll
        for (int r = 0; r < 8; r++) {
            int grow = row0 + trow + r * 8;
            float4 o;
            o.x = 1.0f / (1.0f + __expf(-(acc[r][0] + bgv.x)));
            o.y = 1.0f / (1.0f + __expf(-(acc[r][1] + bgv.y)));
            o.z = 1.0f / (1.0f + __expf(-(acc[r][2] + bgv.z)));
            o.w = 1.0f / (1.0f + __expf(-(acc[r][3] + bgv.w)));
            *((float4*)(g_gate + (size_t)grow * CC + e0)) = o;
        }
    }
}

// ---------------- depthwise conv in smem -----------------------------------
// thread t: channel d = t&31, rows l0..l0+31 with l0 = (t>>5)*32
template <int K>
__device__ __forceinline__ void conv_ip(float* xs, const float* __restrict__ w,
                                        const float* __restrict__ b, int tid) {
    int d  = tid & 31;
    int l0 = (tid >> 5) << 5;
    float wr[K];
    #pragma unroll
    for (int j = 0; j < K; j++) wr[j] = w[d * K + j];
    float bias = b[d];
    const int off = K / 2;
    float out[32];
    #pragma unroll 4
    for (int i = 0; i < 32; i++) {
        int l = l0 + i;
        float acc = bias;
        #pragma unroll
        for (int j = 0; j < K; j++) {
            int ll = l + j - off;
            if (ll >= 0 && ll < 256) acc += xs[ll * 32 + d] * wr[j];
        }
        out[i] = acc;
    }
    __syncthreads();
    #pragma unroll
    for (int i = 0; i < 32; i++) xs[(l0 + i) * 32 + d] = out[i];
    __syncthreads();
}

// ---------------- K3: fused conv + attention + gate ------------------------
// grid = 1024 (= s*H+h); block = 256 (thread = query index)
__global__ void k_attn(const float* __restrict__ seq_mask,
                       const float* __restrict__ qw3, const float* __restrict__ qb3,
                       const float* __restrict__ qw5, const float* __restrict__ qb5,
                       const float* __restrict__ qw7, const float* __restrict__ qb7,
                       const float* __restrict__ kw3, const float* __restrict__ kb3,
                       const float* __restrict__ kw5, const float* __restrict__ kb5,
                       const float* __restrict__ kw7, const float* __restrict__ kb7,
                       const float* __restrict__ vw3, const float* __restrict__ vb3,
                       const float* __restrict__ vw5, const float* __restrict__ vb5,
                       const float* __restrict__ vw7, const float* __restrict__ vb7) {
    extern __shared__ float sm[];
    float* qs  = sm;
    float* ks  = sm + 8192;
    float* vs  = sm + 16384;
    float* msk = sm + 24576;

    int sh  = blockIdx.x;
    int s   = sh >> 2, h = sh & 3;
    int tid = threadIdx.x;
    size_t base = (size_t)sh * 8192;

    for (int i = tid; i < 2048; i += 256) {
        ((float4*)qs)[i] = ((const float4*)(g_q + base))[i];
        ((float4*)ks)[i] = ((const float4*)(g_k + base))[i];
        ((float4*)vs)[i] = ((const float4*)(g_v + base))[i];
    }
    msk[tid] = seq_mask[tid];
    __syncthreads();

    int grp = s >> 6;          // 0: identity, 1: k=3, 2: k=5, 3: k=7
    if (grp == 1) {
        conv_ip<3>(qs, qw3, qb3, tid);
        conv_ip<3>(ks, kw3, kb3, tid);
        conv_ip<3>(vs, vw3, vb3, tid);
    } else if (grp == 2) {
        conv_ip<5>(qs, qw5, qb5, tid);
        conv_ip<5>(ks, kw5, kb5, tid);
        conv_ip<5>(vs, vw5, vb5, tid);
    } else if (grp == 3) {
        conv_ip<7>(qs, qw7, qb7, tid);
        conv_ip<7>(ks, kw7, kb7, tid);
        conv_ip<7>(vs, vw7, vb7, tid);
    }

    // thread = query row
    float q_reg[32];
    {
        const float4* qrow = (const float4*)(qs + tid * 32);
        float4* qr4 = (float4*)q_reg;
        #pragma unroll
        for (int i = 0; i < 8; i++) qr4[i] = qrow[i];
    }

    float o[32];
    #pragma unroll
    for (int i = 0; i < 32; i++) o[i] = 0.0f;
    float lsum = 0.0f;
    const float scale = 0.17677669529663687f;              // 1/sqrt(32)
    const float mask_value = -3.3895313892515355e+34f;     // finfo.min/1e4
    const float* bptr = g_biasT + h * NROW + tid;

    for (int k = 0; k < 256; k++) {
        const float4* kr = (const float4*)(ks + k * 32);
        float dot = 0.0f;
        #pragma unroll
        for (int i = 0; i < 8; i++) {
            float4 kv = kr[i];
            dot += q_reg[4*i+0] * kv.x + q_reg[4*i+1] * kv.y
                 + q_reg[4*i+2] * kv.z + q_reg[4*i+3] * kv.w;
        }
        float logit = dot * scale + bptr[k * 256];
        if (msk[k] <= 0.0f) logit = mask_value;
        float p = __expf(logit);
        lsum += p;
        const float4* vr = (const float4*)(vs + k * 32);
        #pragma unroll
        for (int i = 0; i < 8; i++) {
            float4 vv = vr[i];
            o[4*i+0] += p * vv.x; o[4*i+1] += p * vv.y;
            o[4*i+2] += p * vv.z; o[4*i+3] += p * vv.w;
        }
    }

    float inv = 1.0f / lsum;
    size_t orow = ((size_t)(s * 256 + tid)) * CC + h * 32;
    const float4* g4 = (const float4*)(g_gate + orow);
    float4*       w4 = (float4*)(g_wa + orow);
    #pragma unroll
    for (int i = 0; i < 8; i++) {
        float4 gv = g4[i];
        float4 ov;
        ov.x = o[4*i+0] * inv * gv.x;
        ov.y = o[4*i+1] * inv * gv.y;
        ov.z = o[4*i+2] * inv * gv.z;
        ov.w = o[4*i+3] * inv * gv.w;
        w4[i] = ov;
    }
}

// ---------------- K4: output projection ------------------------------------
__global__ void k_out(const float* __restrict__ wo, const float* __restrict__ bo,
                      float* __restrict__ out) {
    extern __shared__ float smem[];
    float* Ws = smem;
    float* As = smem + 128 * 128;
    int tid = threadIdx.x;

    for (int i = tid; i < 4096; i += 256)
        ((float4*)Ws)[i] = ((const float4*)wo)[i];
    int row0 = blockIdx.x * 64;
    for (int i = tid; i < 2048; i += 256)
        ((float4*)As)[i] = ((const float4*)(g_wa + (size_t)row0 * CC))[i];
    __syncthreads();

    int tcol = tid & 31, trow = tid >> 5;
    float acc[8][4];
    #pragma unroll
    for (int r = 0; r < 8; r++)
        acc[r][0] = acc[r][1] = acc[r][2] = acc[r][3] = 0.0f;

    #pragma unroll 4
    for (int k = 0; k < 128; k++) {
        float4 bf = ((float4*)(Ws + k * 128))[tcol];
        #pragma unroll
        for (int r = 0; r < 8; r++) {
            float a = As[(trow + r * 8) * 128 + k];
            acc[r][0] += a * bf.x;
            acc[r][1] += a * bf.y;
            acc[r][2] += a * bf.z;
            acc[r][3] += a * bf.w;
        }
    }

    int e0 = tcol * 4;
    float4 bov = ((const float4*)bo)[tcol];
    #pragma unroll
    for (int r = 0; r < 8; r++) {
        int grow = row0 + trow + r * 8;
        float4 o = make_float4(acc[r][0] + bov.x, acc[r][1] + bov.y,
                               acc[r][2] + bov.z, acc[r][3] + bov.w);
        *((float4*)(out + (size_t)grow * CC + e0)) = o;
    }
}

// ---------------- launch ----------------------------------------------------
extern "C" void kernel_launch(void* const* d_in, const int* in_sizes, int n_in,
                              void* d_out, int out_size) {
    const float* pair_act = (const float*)d_in[0];
    const float* seq_mask = (const float*)d_in[1];
    const float* ln_g     = (const float*)d_in[2];
    const float* ln_b     = (const float*)d_in[3];
    const float* w_pair   = (const float*)d_in[4];
    const float* wq       = (const float*)d_in[5];
    const float* wk       = (const float*)d_in[6];
    const float* wv       = (const float*)d_in[7];
    const float* wg       = (const float*)d_in[8];
    const float* bg       = (const float*)d_in[9];
    const float* wo       = (const float*)d_in[10];
    const float* bo       = (const float*)d_in[11];
    const float* qw3 = (const float*)d_in[12]; const float* qb3 = (const float*)d_in[13];
    const float* qw5 = (const float*)d_in[14]; const float* qb5 = (const float*)d_in[15];
    const float* qw7 = (const float*)d_in[16]; const float* qb7 = (const float*)d_in[17];
    const float* kw3 = (const float*)d_in[18]; const float* kb3 = (const float*)d_in[19];
    const float* kw5 = (const float*)d_in[20]; const float* kb5 = (const float*)d_in[21];
    const float* kw7 = (const float*)d_in[22]; const float* kb7 = (const float*)d_in[23];
    const float* vw3 = (const float*)d_in[24]; const float* vb3 = (const float*)d_in[25];
    const float* vw5 = (const float*)d_in[26]; const float* vb5 = (const float*)d_in[27];
    const float* vw7 = (const float*)d_in[28]; const float* vb7 = (const float*)d_in[29];
    float* out = (float*)d_out;

    const int gemm_smem = (128 * 128 + 64 * 128) * sizeof(float);   // 98304
    const int attn_smem = (3 * 8192 + 256) * sizeof(float);         // 99328
    cudaFuncSetAttribute(k_qkvg, cudaFuncAttributeMaxDynamicSharedMemorySize, gemm_smem);
    cudaFuncSetAttribute(k_out,  cudaFuncAttributeMaxDynamicSharedMemorySize, gemm_smem);
    cudaFuncSetAttribute(k_attn, cudaFuncAttributeMaxDynamicSharedMemorySize, attn_smem);

    dim3 lnb(32, 8);
    k_ln_bias<<<NROW / 8, lnb>>>(pair_act, ln_g, ln_b, w_pair);

    dim3 g2(NROW / 64, 4);
    k_qkvg<<<g2, 256, gemm_smem>>>(wq, wk, wv, wg, bg);

    k_attn<<<LL * HH, 256, attn_smem>>>(seq_mask,
        qw3, qb3, qw5, qb5, qw7, qb7,
        kw3, kb3, kw5, kb5, kw7, kb7,
        vw3, vb3, vw5, vb5, vw7, vb7);

    k_out<<<NROW / 64, 256, gemm_smem>>>(wo, bo, out);
}

// round 4
// speedup vs baseline: 2.2392x; 2.2392x over previous
#include <cuda_runtime.h>
#include <math.h>

#define LL 256
#define CC 128
#define HH 4
#define DD 32
#define NROW (LL*LL)

typedef unsigned int uint32;

// ---------------- scratch ---------------------------------------------------
__device__ float g_x   [NROW*CC];
__device__ float g_biasT[HH*LL*LL];  // [h][k][q]
__device__ float g_q   [NROW*CC];    // [(s*H+h)*L + l][d]
__device__ float g_k   [NROW*CC];
__device__ float g_v   [NROW*CC];
__device__ float g_gate[NROW*CC];
__device__ float g_wa  [NROW*CC];

// ---------------- helpers ---------------------------------------------------
__device__ __forceinline__ float tf32r(float x) {
    uint32 u;
    asm("cvt.rna.tf32.f32 %0, %1;" : "=r"(u) : "f"(x));
    return __uint_as_float(u);
}

__device__ __forceinline__ void mma8(float4& d, const uint32* a, const uint32* b) {
    asm volatile(
        "mma.sync.aligned.m16n8k8.row.col.f32.tf32.tf32.f32 "
        "{%0,%1,%2,%3},{%4,%5,%6,%7},{%8,%9},{%0,%1,%2,%3};\n"
        : "+f"(d.x), "+f"(d.y), "+f"(d.z), "+f"(d.w)
        : "r"(a[0]), "r"(a[1]), "r"(a[2]), "r"(a[3]), "r"(b[0]), "r"(b[1]));
}

// ---------------- K1: LayerNorm + pair bias --------------------------------
__global__ void k_ln_bias(const float* __restrict__ pa,
                          const float* __restrict__ lng,
                          const float* __restrict__ lnb,
                          const float* __restrict__ wp) {
    int row  = blockIdx.x * 8 + threadIdx.y;
    int lane = threadIdx.x;
    const float4* src = (const float4*)(pa + (size_t)row * CC);
    float4 v = src[lane];

    float sum = v.x + v.y + v.z + v.w;
    #pragma unroll
    for (int o = 16; o; o >>= 1) sum += __shfl_xor_sync(0xffffffffu, sum, o);
    float mean = sum * (1.0f / CC);

    float d0 = v.x - mean, d1 = v.y - mean, d2 = v.z - mean, d3 = v.w - mean;
    float vs = d0*d0 + d1*d1 + d2*d2 + d3*d3;
    #pragma unroll
    for (int o = 16; o; o >>= 1) vs += __shfl_xor_sync(0xffffffffu, vs, o);
    float rstd = rsqrtf(vs * (1.0f / CC) + 1e-5f);

    int c = lane * 4;
    float4 gg = ((const float4*)lng)[lane];
    float4 bb = ((const float4*)lnb)[lane];
    float y0 = d0 * rstd * gg.x + bb.x;
    float y1 = d1 * rstd * gg.y + bb.y;
    float y2 = d2 * rstd * gg.z + bb.z;
    float y3 = d3 * rstd * gg.w + bb.w;
    ((float4*)(g_x + (size_t)row * CC))[lane] = make_float4(y0, y1, y2, y3);

    float4 w0 = ((const float4*)wp)[c + 0];
    float4 w1 = ((const float4*)wp)[c + 1];
    float4 w2 = ((const float4*)wp)[c + 2];
    float4 w3 = ((const float4*)wp)[c + 3];
    float a0 = y0*w0.x + y1*w1.x + y2*w2.x + y3*w3.x;
    float a1 = y0*w0.y + y1*w1.y + y2*w2.y + y3*w3.y;
    float a2 = y0*w0.z + y1*w1.z + y2*w2.z + y3*w3.z;
    float a3 = y0*w0.w + y1*w1.w + y2*w2.w + y3*w3.w;
    #pragma unroll
    for (int o = 16; o; o >>= 1) {
        a0 += __shfl_xor_sync(0xffffffffu, a0, o);
        a1 += __shfl_xor_sync(0xffffffffu, a1, o);
        a2 += __shfl_xor_sync(0xffffffffu, a2, o);
        a3 += __shfl_xor_sync(0xffffffffu, a3, o);
    }
    if (lane == 0) {
        int i = row >> 8;     // q
        int j = row & 255;    // k
        g_biasT[0*NROW + j*LL + i] = a0;
        g_biasT[1*NROW + j*LL + i] = a1;
        g_biasT[2*NROW + j*LL + i] = a2;
        g_biasT[3*NROW + j*LL + i] = a3;
    }
}

// ---------------- K2: x @ {wq,wk,wv,wg} via tf32 mma ------------------------
// grid (512, 4), block 256. Tile 128 rows x 128 cols.
#define GST 132
__global__ void k_qkvg(const float* __restrict__ wq, const float* __restrict__ wk,
                       const float* __restrict__ wv, const float* __restrict__ wg,
                       const float* __restrict__ bg) {
    extern __shared__ float smem[];
    float* As = smem;             // 128 x GST
    float* Ws = smem + 128*GST;   // 128 x GST

    int m = blockIdx.y;
    const float* W = (m == 0) ? wq : (m == 1) ? wk : (m == 2) ? wv : wg;
    int tid = threadIdx.x;
    int row0 = blockIdx.x * 128;

    for (int i = tid; i < 4096; i += 256) {
        int r = i >> 5, c4 = i & 31;
        float4 a = ((const float4*)(g_x + (size_t)(row0 + r) * CC))[c4];
        a.x = tf32r(a.x); a.y = tf32r(a.y); a.z = tf32r(a.z); a.w = tf32r(a.w);
        ((float4*)(As + r * GST))[c4] = a;
        float4 w = ((const float4*)W)[i];
        w.x = tf32r(w.x); w.y = tf32r(w.y); w.z = tf32r(w.z); w.w = tf32r(w.w);
        ((float4*)(Ws + r * GST))[c4] = w;
    }
    __syncthreads();

    int lane = tid & 31, warp = tid >> 5;
    int g = lane >> 2, t = lane & 3;
    int wm = (warp >> 2) * 64, wn = (warp & 3) * 32;

    float4 acc[4][4];
    #pragma unroll
    for (int mi = 0; mi < 4; mi++)
        #pragma unroll
        for (int ni = 0; ni < 4; ni++)
            acc[mi][ni] = make_float4(0.f, 0.f, 0.f, 0.f);

    #pragma unroll
    for (int k0 = 0; k0 < 128; k0 += 8) {
        uint32 a[4][4], b[4][2];
        #pragma unroll
        for (int mi = 0; mi < 4; mi++) {
            const float* ap = As + (wm + mi*16 + g) * GST + k0 + t;
            a[mi][0] = __float_as_uint(ap[0]);
            a[mi][1] = __float_as_uint(ap[8*GST]);
            a[mi][2] = __float_as_uint(ap[4]);
            a[mi][3] = __float_as_uint(ap[8*GST + 4]);
        }
        #pragma unroll
        for (int ni = 0; ni < 4; ni++) {
            const float* bp = Ws + (k0 + t) * GST + wn + ni*8 + g;
            b[ni][0] = __float_as_uint(bp[0]);
            b[ni][1] = __float_as_uint(bp[4*GST]);
        }
        #pragma unroll
        for (int mi = 0; mi < 4; mi++)
            #pragma unroll
            for (int ni = 0; ni < 4; ni++)
                mma8(acc[mi][ni], a[mi], b[ni]);
    }

    #pragma unroll
    for (int mi = 0; mi < 4; mi++) {
        #pragma unroll
        for (int ni = 0; ni < 4; ni++) {
            int r0   = row0 + wm + mi*16 + g;
            int col0 = wn + ni*8 + 2*t;
            float4 c = acc[mi][ni];
            if (m < 3) {
                float* dst = (m == 0) ? g_q : (m == 1) ? g_k : g_v;
                int h = col0 >> 5, d = col0 & 31;
                int s0 = r0 >> 8, l0 = r0 & 255;
                float2 v01 = make_float2(c.x, c.y);
                float2 v23 = make_float2(c.z, c.w);
                *(float2*)(dst + ((size_t)((s0*4 + h)*256 + l0)) * 32 + d) = v01;
                int r1 = r0 + 8;
                int s1 = r1 >> 8, l1 = r1 & 255;
                *(float2*)(dst + ((size_t)((s1*4 + h)*256 + l1)) * 32 + d) = v23;
            } else {
                float b0 = bg[col0], b1 = bg[col0 + 1];
                float2 v01 = make_float2(1.0f/(1.0f + __expf(-(c.x + b0))),
                                         1.0f/(1.0f + __expf(-(c.y + b1))));
                float2 v23 = make_float2(1.0f/(1.0f + __expf(-(c.z + b0))),
                                         1.0f/(1.0f + __expf(-(c.w + b1))));
                *(float2*)(g_gate + (size_t)r0 * CC + col0)       = v01;
                *(float2*)(g_gate + (size_t)(r0 + 8) * CC + col0) = v23;
            }
        }
    }
}

// ---------------- depthwise conv in smem (stride 36) ------------------------
#define AST 36
template <int K>
__device__ __forceinline__ void conv_ip(float* xs, const float* __restrict__ w,
                                        const float* __restrict__ b, int tid) {
    int d  = tid & 31;
    int l0 = (tid >> 5) << 5;
    float wr[K];
    #pragma unroll
    for (int j = 0; j < K; j++) wr[j] = w[d * K + j];
    float bias = b[d];
    const int off = K / 2;
    float out[32];
    #pragma unroll 4
    for (int i = 0; i < 32; i++) {
        int l = l0 + i;
        float acc = bias;
        #pragma unroll
        for (int j = 0; j < K; j++) {
            int ll = l + j - off;
            if (ll >= 0 && ll < 256) acc += xs[ll * AST + d] * wr[j];
        }
        out[i] = acc;
    }
    __syncthreads();
    #pragma unroll
    for (int i = 0; i < 32; i++) xs[(l0 + i) * AST + d] = out[i];
    __syncthreads();
}

// ---------------- K3: conv + tf32-mma attention + gate ----------------------
// grid 1024 (= s*H + h), block 256 (8 warps; warp w -> query rows [32w,32w+32))
__global__ void k_attn(const float* __restrict__ seq_mask,
                       const float* __restrict__ qw3, const float* __restrict__ qb3,
                       const float* __restrict__ qw5, const float* __restrict__ qb5,
                       const float* __restrict__ qw7, const float* __restrict__ qb7,
                       const float* __restrict__ kw3, const float* __restrict__ kb3,
                       const float* __restrict__ kw5, const float* __restrict__ kb5,
                       const float* __restrict__ kw7, const float* __restrict__ kb7,
                       const float* __restrict__ vw3, const float* __restrict__ vb3,
                       const float* __restrict__ vw5, const float* __restrict__ vb5,
                       const float* __restrict__ vw7, const float* __restrict__ vb7) {
    extern __shared__ float sm[];
    float* qs  = sm;             // 256*36
    float* ks  = qs + 256*AST;
    float* vs  = ks + 256*AST;
    float* ps  = vs + 256*AST;   // 8 * 32*36
    float* bs  = ps + 8*32*AST;  // 8 * 32*36
    float* msk = bs + 8*32*AST;  // 256

    int sh  = blockIdx.x;
    int si  = sh >> 2, h = sh & 3;
    int tid = threadIdx.x;
    size_t base = (size_t)sh * 8192;

    for (int i = tid; i < 2048; i += 256) {
        int r = i >> 3, c4 = i & 7;
        ((float4*)(qs + r*AST))[c4] = ((const float4*)(g_q + base))[i];
        ((float4*)(ks + r*AST))[c4] = ((const float4*)(g_k + base))[i];
        ((float4*)(vs + r*AST))[c4] = ((const float4*)(g_v + base))[i];
    }
    msk[tid] = seq_mask[tid];
    __syncthreads();

    int grp = si >> 6;
    if (grp == 1) {
        conv_ip<3>(qs, qw3, qb3, tid); conv_ip<3>(ks, kw3, kb3, tid); conv_ip<3>(vs, vw3, vb3, tid);
    } else if (grp == 2) {
        conv_ip<5>(qs, qw5, qb5, tid); conv_ip<5>(ks, kw5, kb5, tid); conv_ip<5>(vs, vw5, vb5, tid);
    } else if (grp == 3) {
        conv_ip<7>(qs, qw7, qb7, tid); conv_ip<7>(ks, kw7, kb7, tid); conv_ip<7>(vs, vw7, vb7, tid);
    }

    // round q/k/v to tf32 in place (q carries the 1/sqrt(D) scale)
    const float scale = 0.17677669529663687f;
    for (int r = tid >> 3; r < 256; r += 32) {
        int c4 = (tid & 7) * 4;
        float* qp = qs + r*AST + c4;
        qp[0] = tf32r(qp[0]*scale); qp[1] = tf32r(qp[1]*scale);
        qp[2] = tf32r(qp[2]*scale); qp[3] = tf32r(qp[3]*scale);
        float* kp = ks + r*AST + c4;
        kp[0] = tf32r(kp[0]); kp[1] = tf32r(kp[1]); kp[2] = tf32r(kp[2]); kp[3] = tf32r(kp[3]);
        float* vp = vs + r*AST + c4;
        vp[0] = tf32r(vp[0]); vp[1] = tf32r(vp[1]); vp[2] = tf32r(vp[2]); vp[3] = tf32r(vp[3]);
    }
    __syncthreads();

    int warp = tid >> 5, lane = tid & 31;
    int g = lane >> 2, t = lane & 3;
    int qm = warp * 32;
    float* pw = ps + warp * 32*AST;
    float* bw = bs + warp * 32*AST;
    const float* bT = g_biasT + (size_t)h * NROW;

    float4 o[2][4];
    #pragma unroll
    for (int mi = 0; mi < 2; mi++)
        #pragma unroll
        for (int ni = 0; ni < 4; ni++) o[mi][ni] = make_float4(0.f, 0.f, 0.f, 0.f);
    float rs[2][2] = {{0.f, 0.f}, {0.f, 0.f}};

    for (int kc = 0; kc < 256; kc += 32) {
        // stage bias chunk [32 k][32 q] into bw ([k][q], stride 36)
        {
            int kl0 = lane >> 3;
            int qv  = (lane & 7) * 4;
            #pragma unroll
            for (int i = 0; i < 8; i++) {
                int kl = i*4 + kl0;
                float4 bvv = *(const float4*)(bT + (size_t)(kc + kl)*256 + qm + qv);
                *(float4*)(bw + kl*AST + qv) = bvv;
            }
        }
        __syncwarp();

        // S = Q x K^T for this key chunk
        float4 s[2][4];
        #pragma unroll
        for (int mi = 0; mi < 2; mi++)
            #pragma unroll
            for (int ni = 0; ni < 4; ni++) s[mi][ni] = make_float4(0.f, 0.f, 0.f, 0.f);

        #pragma unroll
        for (int k0 = 0; k0 < 32; k0 += 8) {
            uint32 a[2][4], b[4][2];
            #pragma unroll
            for (int mi = 0; mi < 2; mi++) {
                const float* ap = qs + (qm + mi*16 + g)*AST + k0 + t;
                a[mi][0] = __float_as_uint(ap[0]);
                a[mi][1] = __float_as_uint(ap[8*AST]);
                a[mi][2] = __float_as_uint(ap[4]);
                a[mi][3] = __float_as_uint(ap[8*AST + 4]);
            }
            #pragma unroll
            for (int ni = 0; ni < 4; ni++) {
                const float* bp = ks + (kc + ni*8 + g)*AST + k0 + t;
                b[ni][0] = __float_as_uint(bp[0]);
                b[ni][1] = __float_as_uint(bp[4]);
            }
            #pragma unroll
            for (int mi = 0; mi < 2; mi++)
                #pragma unroll
                for (int ni = 0; ni < 4; ni++)
                    mma8(s[mi][ni], a[mi], b[ni]);
        }

        // bias + mask + exp; write P (tf32) to per-warp smem
        #pragma unroll
        for (int mi = 0; mi < 2; mi++) {
            #pragma unroll
            for (int ni = 0; ni < 4; ni++) {
                int kcol = kc + ni*8 + 2*t;
                float m0 = msk[kcol], m1 = msk[kcol + 1];
                const float* bb = bw + (ni*8 + 2*t)*AST + mi*16 + g;
                float b00 = bb[0], b01 = bb[AST], b10 = bb[8], b11 = bb[AST + 8];
                float4 sv = s[mi][ni];
                float p00 = (m0 > 0.f) ? __expf(sv.x + b00) : 0.f;
                float p01 = (m1 > 0.f) ? __expf(sv.y + b01) : 0.f;
                float p10 = (m0 > 0.f) ? __expf(sv.z + b10) : 0.f;
                float p11 = (m1 > 0.f) ? __expf(sv.w + b11) : 0.f;
                rs[mi][0] += p00 + p01;
                rs[mi][1] += p10 + p11;
                float* pp = pw + (mi*16 + g)*AST + ni*8 + 2*t;
                *(float2*)pp          = make_float2(tf32r(p00), tf32r(p01));
                *(float2*)(pp + 8*AST) = make_float2(tf32r(p10), tf32r(p11));
            }
        }
        __syncwarp();

        // O += P x V
        #pragma unroll
        for (int k0 = 0; k0 < 32; k0 += 8) {
            uint32 a[2][4], b[4][2];
            #pragma unroll
            for (int mi = 0; mi < 2; mi++) {
                const float* ap = pw + (mi*16 + g)*AST + k0 + t;
                a[mi][0] = __float_as_uint(ap[0]);
                a[mi][1] = __float_as_uint(ap[8*AST]);
                a[mi][2] = __float_as_uint(ap[4]);
                a[mi][3] = __float_as_uint(ap[8*AST + 4]);
            }
            #pragma unroll
            for (int ni = 0; ni < 4; ni++) {
                const float* bp = vs + (kc + k0 + t)*AST + ni*8 + g;
                b[ni][0] = __float_as_uint(bp[0]);
                b[ni][1] = __float_as_uint(bp[4*AST]);
            }
            #pragma unroll
            for (int mi = 0; mi < 2; mi++)
                #pragma unroll
                for (int ni = 0; ni < 4; ni++)
                    mma8(o[mi][ni], a[mi], b[ni]);
        }
        __syncwarp();
    }

    // row-sum reduce across the quad, normalize, gate, store
    float inv[2][2];
    #pragma unroll
    for (int mi = 0; mi < 2; mi++) {
        #pragma unroll
        for (int r = 0; r < 2; r++) {
            float v = rs[mi][r];
            v += __shfl_xor_sync(0xffffffffu, v, 1);
            v += __shfl_xor_sync(0xffffffffu, v, 2);
            inv[mi][r] = 1.0f / v;
        }
    }

    #pragma unroll
    for (int mi = 0; mi < 2; mi++) {
        #pragma unroll
        for (int ni = 0; ni < 4; ni++) {
            int q0 = qm + mi*16 + g;
            int d0 = ni*8 + 2*t;
            size_t r0 = ((size_t)(si*256 + q0)) * CC + h*32 + d0;
            float2 g01 = *(const float2*)(g_gate + r0);
            float2 g23 = *(const float2*)(g_gate + r0 + 8*CC);
            float4 ov = o[mi][ni];
            *(float2*)(g_wa + r0) =
                make_float2(ov.x * inv[mi][0] * g01.x, ov.y * inv[mi][0] * g01.y);
            *(float2*)(g_wa + r0 + 8*CC) =
                make_float2(ov.z * inv[mi][1] * g23.x, ov.w * inv[mi][1] * g23.y);
        }
    }
}

// ---------------- K4: output projection via tf32 mma ------------------------
__global__ void k_out(const float* __restrict__ wo, const float* __restrict__ bo,
                      float* __restrict__ out) {
    extern __shared__ float smem[];
    float* As = smem;
    float* Ws = smem + 128*GST;
    int tid = threadIdx.x;
    int row0 = blockIdx.x * 128;

    for (int i = tid; i < 4096; i += 256) {
        int r = i >> 5, c4 = i & 31;
        float4 a = ((const float4*)(g_wa + (size_t)(row0 + r) * CC))[c4];
        a.x = tf32r(a.x); a.y = tf32r(a.y); a.z = tf32r(a.z); a.w = tf32r(a.w);
        ((float4*)(As + r * GST))[c4] = a;
        float4 w = ((const float4*)wo)[i];
        w.x = tf32r(w.x); w.y = tf32r(w.y); w.z = tf32r(w.z); w.w = tf32r(w.w);
        ((float4*)(Ws + r * GST))[c4] = w;
    }
    __syncthreads();

    int lane = tid & 31, warp = tid >> 5;
    int g = lane >> 2, t = lane & 3;
    int wm = (warp >> 2) * 64, wn = (warp & 3) * 32;

    float4 acc[4][4];
    #pragma unroll
    for (int mi = 0; mi < 4; mi++)
        #pragma unroll
        for (int ni = 0; ni < 4; ni++)
            acc[mi][ni] = make_float4(0.f, 0.f, 0.f, 0.f);

    #pragma unroll
    for (int k0 = 0; k0 < 128; k0 += 8) {
        uint32 a[4][4], b[4][2];
        #pragma unroll
        for (int mi = 0; mi < 4; mi++) {
            const float* ap = As + (wm + mi*16 + g) * GST + k0 + t;
            a[mi][0] = __float_as_uint(ap[0]);
            a[mi][1] = __float_as_uint(ap[8*GST]);
            a[mi][2] = __float_as_uint(ap[4]);
            a[mi][3] = __float_as_uint(ap[8*GST + 4]);
        }
        #pragma unroll
        for (int ni = 0; ni < 4; ni++) {
            const float* bp = Ws + (k0 + t) * GST + wn + ni*8 + g;
            b[ni][0] = __float_as_uint(bp[0]);
            b[ni][1] = __float_as_uint(bp[4*GST]);
        }
        #pragma unroll
        for (int mi = 0; mi < 4; mi++)
            #pragma unroll
            for (int ni = 0; ni < 4; ni++)
                mma8(acc[mi][ni], a[mi], b[ni]);
    }

    #pragma unroll
    for (int mi = 0; mi < 4; mi++) {
        #pragma unroll
        for (int ni = 0; ni < 4; ni++) {
            int r0   = row0 + wm + mi*16 + g;
            int col0 = wn + ni*8 + 2*t;
            float b0 = bo[col0], b1 = bo[col0 + 1];
            float4 c = acc[mi][ni];
            *(float2*)(out + (size_t)r0 * CC + col0) =
                make_float2(c.x + b0, c.y + b1);
            *(float2*)(out + (size_t)(r0 + 8) * CC + col0) =
                make_float2(c.z + b0, c.w + b1);
        }
    }
}

// ---------------- launch -----------------------------------------------------
extern "C" void kernel_launch(void* const* d_in, const int* in_sizes, int n_in,
                              void* d_out, int out_size) {
    const float* pair_act = (const float*)d_in[0];
    const float* seq_mask = (const float*)d_in[1];
    const float* ln_g     = (const float*)d_in[2];
    const float* ln_b     = (const float*)d_in[3];
    const float* w_pair   = (const float*)d_in[4];
    const float* wq       = (const float*)d_in[5];
    const float* wk       = (const float*)d_in[6];
    const float* wv       = (const float*)d_in[7];
    const float* wg       = (const float*)d_in[8];
    const float* bg       = (const float*)d_in[9];
    const float* wo       = (const float*)d_in[10];
    const float* bo       = (const float*)d_in[11];
    const float* qw3 = (const float*)d_in[12]; const float* qb3 = (const float*)d_in[13];
    const float* qw5 = (const float*)d_in[14]; const float* qb5 = (const float*)d_in[15];
    const float* qw7 = (const float*)d_in[16]; const float* qb7 = (const float*)d_in[17];
    const float* kw3 = (const float*)d_in[18]; const float* kb3 = (const float*)d_in[19];
    const float* kw5 = (const float*)d_in[20]; const float* kb5 = (const float*)d_in[21];
    const float* kw7 = (const float*)d_in[22]; const float* kb7 = (const float*)d_in[23];
    const float* vw3 = (const float*)d_in[24]; const float* vb3 = (const float*)d_in[25];
    const float* vw5 = (const float*)d_in[26]; const float* vb5 = (const float*)d_in[27];
    const float* vw7 = (const float*)d_in[28]; const float* vb7 = (const float*)d_in[29];
    float* out = (float*)d_out;

    const int gemm_smem = 2 * 128 * GST * sizeof(float);               // 135168
    const int attn_smem = (3*256*AST + 2*8*32*AST + 256) * sizeof(float); // 185344
    cudaFuncSetAttribute(k_qkvg, cudaFuncAttributeMaxDynamicSharedMemorySize, gemm_smem);
    cudaFuncSetAttribute(k_out,  cudaFuncAttributeMaxDynamicSharedMemorySize, gemm_smem);
    cudaFuncSetAttribute(k_attn, cudaFuncAttributeMaxDynamicSharedMemorySize, attn_smem);

    dim3 lnb(32, 8);
    k_ln_bias<<<NROW / 8, lnb>>>(pair_act, ln_g, ln_b, w_pair);

    dim3 g2(NROW / 128, 4);
    k_qkvg<<<g2, 256, gemm_smem>>>(wq, wk, wv, wg, bg);

    k_attn<<<LL * HH, 256, attn_smem>>>(seq_mask,
        qw3, qb3, qw5, qb5, qw7, qb7,
        kw3, kb3, kw5, kb5, kw7, kb7,
        vw3, vb3, vw5, vb5, vw7, vb7);

    k_out<<<NROW / 128, 256, gemm_smem>>>(wo, bo, out);
}